// round 8
// baseline (speedup 1.0000x reference)
#include <cuda_runtime.h>
#include <cstdint>

namespace {

typedef unsigned int u32;

constexpr int AST = 44;                    // A smem row stride (words)
constexpr int BST = 264;                   // B smem row stride (words), 264 % 32 == 8
constexpr int A_WORDS = 64 * AST;          // 2816
constexpr int B_WORDS = 16 * BST;          // 4224 (16 rows: 4 ch x (3 raw + Sn))
constexpr int SMEM_TOTAL = (A_WORDS + B_WORDS) * 4;  // 28160 B

// Packed weights: tf32 (rna) bits, row oc (64), col k = i*10 + t (640).
// taps 0..8 = conv3x3 (ky*3+kx), tap 9 = collapsed quadratic matrix M[o][i].
__device__ u32 g_A[64 * 640];
__device__ float g_bias[64];

__device__ __forceinline__ u32 to_tf32(float f) {
    u32 r;
    asm("cvt.rna.tf32.f32 %0, %1;" : "=r"(r) : "f"(f));
    return r;
}

__device__ __forceinline__ void mma_tf32(float* d, const u32* a, u32 b0, u32 b1) {
    asm volatile(
        "mma.sync.aligned.m16n8k8.row.col.f32.tf32.tf32.f32 "
        "{%0,%1,%2,%3}, {%4,%5,%6,%7}, {%8,%9}, {%0,%1,%2,%3};"
        : "+f"(d[0]), "+f"(d[1]), "+f"(d[2]), "+f"(d[3])
        : "r"(a[0]), "r"(a[1]), "r"(a[2]), "r"(a[3]), "r"(b0), "r"(b1));
}

__device__ __forceinline__ void ldmx4(u32* r, u32 addr) {
    asm volatile("ldmatrix.sync.aligned.m8n8.x4.shared.b16 {%0,%1,%2,%3}, [%4];"
                 : "=r"(r[0]), "=r"(r[1]), "=r"(r[2]), "=r"(r[3]) : "r"(addr));
}

__device__ __forceinline__ u32 smem_u32(const void* p) {
    u32 a;
    asm("{ .reg .u64 t; cvta.to.shared.u64 t, %1; cvt.u32.u64 %0, t; }" : "=r"(a) : "l"(p));
    return a;
}

__device__ __forceinline__ void cp_async16(u32 dst, const void* src) {
    asm volatile("cp.async.cg.shared.global [%0], [%1], 16;"
                 :: "r"(dst), "l"(src) : "memory");
}

// k (0..39 within iter) -> B smem word offset (row*BST + dx)
__device__ __forceinline__ int b_off(int k) {
    int c = k / 10, t = k - c * 10;
    int j = (t < 9) ? (t / 3) : 3;       // raw row 0..2 or Sn row 3
    int dx = (t < 9) ? (t % 3 - 1) : 0;
    return (c * 4 + j) * BST + dx;
}

// grid 64 (channel i) x 256 threads (64 oc x 4 q-slices)
__global__ void precompute_kernel(const float* __restrict__ lw,
                                  const float* __restrict__ lb,
                                  const float* __restrict__ w2aw,
                                  const float* __restrict__ w2ab,
                                  const float* __restrict__ w2bw,
                                  const float* __restrict__ w2bb) {
    const int i = blockIdx.x;
    const int o = (int)threadIdx.x & 63;
    const int qq = (int)threadIdx.x >> 6;
    __shared__ float red[4][64];

    {
        const float* wb = w2bw + qq * 4096 + o * 64;
        const float* wa = w2aw + qq * 4096 + i;
        float m = 0.f;
#pragma unroll 8
        for (int mm = 0; mm < 64; mm++) m = fmaf(wb[mm], wa[mm * 64], m);
        red[qq][o] = m;
    }
    __syncthreads();

    if (qq == 0) {
        float w[10];
#pragma unroll
        for (int t = 0; t < 9; t++) w[t] = lw[(o * 64 + i) * 9 + t];
        w[9] = ((red[0][o] + red[1][o]) + (red[2][o] + red[3][o]));  // Sn tap
#pragma unroll
        for (int t = 0; t < 10; t++)
            g_A[o * 640 + i * 10 + t] = to_tf32(w[t]);

        if (i == 0) {
            float c = 0.f;
            for (int q = 0; q < 4; q++) {
                const float* wb = w2bw + q * 4096 + o * 64;
                const float* ab = w2ab + q * 64;
                float hh = 0.f;
#pragma unroll 8
                for (int mm = 0; mm < 64; mm++) hh = fmaf(wb[mm], ab[mm], hh);
                c += hh + w2bb[q * 64 + o];
            }
            g_bias[o] = lb[o] + c;
        }
    }
}

// 2048 CTAs (blockIdx.x = b*256 + y), 256 threads (8 warps), 2 CTAs/SM.
// Warp w owns output tile oc[0..63] x px[w*32 .. w*32+31].
// Smem: As [64 oc][44]; Bs [16 rows][264]: per channel c (0..3) rows c*4+{0,1,2}
// = zero-padded image rows y-1,y,y+1 at cols -1..256 (index col+1), row c*4+3 = Sn.
// Conv taps read raw rows at offset dx; boundary handling is purely structural.
__global__ __launch_bounds__(256, 2)
void volterra_hmma(const float* __restrict__ x, float* __restrict__ out) {
    extern __shared__ u32 smem[];
    const u32 As_b = smem_u32(smem);
    u32* Bu = smem + A_WORDS;
    float* Bf = (float*)Bu;

    const int tid = (int)threadIdx.x;
    const int w = tid >> 5;
    const int lane = tid & 31;
    const int b = (int)blockIdx.x >> 8;
    const int y = (int)blockIdx.x & 255;
    const int cx = tid;  // this thread's pixel column

    const int ym1 = (y - 1) & 255, yp1 = (y + 1) & 255;
    const int xm1 = (cx - 1) & 255, xp1 = (cx + 1) & 255;
    const int oA = (ym1 << 8), oB = (y << 8), oC = (yp1 << 8);
    const float* xit = x + ((size_t)b << 22);  // advances 4 channels / iter

    const float rm0 = (y == 0) ? 0.f : 1.f;    // row y-1 outside image
    const float rm2 = (y == 255) ? 0.f : 1.f;  // row y+1 outside image

    // ldmatrix lane-role (A fragments)
    const int lrow = lane & 15;
    const int lcol = (lane >> 4) * 4;

    // B scalar-fragment roles + per-lane k->address tables (constant across iters)
    const int r_ = lane >> 2, cc_ = lane & 3;
    const int pxbase = 1 + w * 32 + r_;
    int off0[5], off1[5];
#pragma unroll
    for (int k5 = 0; k5 < 5; k5++) {
        off0[k5] = b_off(k5 * 8 + cc_) + pxbase;
        off1[k5] = b_off(k5 * 8 + cc_ + 4) + pxbase;
    }

    // zero the halo columns once (cols 0 and 257 of each of 16 rows; never rewritten)
    if (tid < 16) {
        Bf[tid * BST] = 0.f;
        Bf[tid * BST + 257] = 0.f;
    }

    float acc[4][4][4];
#pragma unroll
    for (int m = 0; m < 4; m++)
#pragma unroll
        for (int n = 0; n < 4; n++)
#pragma unroll
            for (int r = 0; r < 4; r++) acc[m][n][r] = 0.f;

    // A-stage roles: 640 quads over 256 threads, 3 passes
    int aq_off[3], aq_src[3];
#pragma unroll
    for (int p = 0; p < 3; p++) {
        int idx = tid + p * 256;
        int oc = idx / 10, j = idx - oc * 10;
        aq_off[p] = (oc * AST + j * 4) << 2;
        aq_src[p] = oc * 640 + j * 4;
    }
    const u32* gA0 = g_A;  // advances by 40 per iter

#pragma unroll 1
    for (int iter = 0; iter < 16; iter++) {
        __syncthreads();  // previous iteration's smem reads complete

        // ---- stage A[64][40] via cp.async ----
#pragma unroll
        for (int p = 0; p < 3; p++) {
            if (tid + p * 256 < 640)
                cp_async16(As_b + (u32)aq_off[p], gA0 + aq_src[p]);
        }
        asm volatile("cp.async.commit_group;" ::: "memory");

        // ---- build B: 4 channels x (3 zero-padded raw rows + Sn row) ----
#pragma unroll
        for (int c = 0; c < 4; c++) {
            const float* xc = xit + ((size_t)c << 16);
            float v0 = __ldg(xc + oA + cx);
            float v1 = __ldg(xc + oB + cx);
            float v2 = __ldg(xc + oC + cx);

            // vertical partial sums for the circular 3x3 box
            float c1 = (v0 + v1) + v2;
            float c2 = fmaf(v0, v0, fmaf(v1, v1, v2 * v2));
            float c1m = __shfl_up_sync(0xffffffffu, c1, 1);
            float c2m = __shfl_up_sync(0xffffffffu, c2, 1);
            float c1p = __shfl_down_sync(0xffffffffu, c1, 1);
            float c2p = __shfl_down_sync(0xffffffffu, c2, 1);
            if (lane == 0) {  // left neighbor is in another warp: reload circularly
                float u0 = __ldg(xc + oA + xm1);
                float u1 = __ldg(xc + oB + xm1);
                float u2 = __ldg(xc + oC + xm1);
                c1m = (u0 + u1) + u2;
                c2m = fmaf(u0, u0, fmaf(u1, u1, u2 * u2));
            }
            if (lane == 31) {  // right neighbor
                float u0 = __ldg(xc + oA + xp1);
                float u1 = __ldg(xc + oB + xp1);
                float u2 = __ldg(xc + oC + xp1);
                c1p = (u0 + u1) + u2;
                c2p = fmaf(u0, u0, fmaf(u1, u1, u2 * u2));
            }
            float s = (c1m + c1) + c1p;
            float s2 = (c2m + c2) + c2p;
            float Sn = fmaf(s, s, s2) * (1.0f / 90.0f);

            float* row = Bf + (c * 4) * BST + 1 + cx;
            row[0 * BST] = v0 * rm0;   // zero-padded for conv taps
            row[1 * BST] = v1;
            row[2 * BST] = v2 * rm2;
            row[3 * BST] = Sn;
        }
        xit += (size_t)4 << 16;
        gA0 += 40;

        asm volatile("cp.async.wait_group 0;" ::: "memory");
        __syncthreads();

        // ---- 5 k8-steps; A via ldmatrix, B via shifted scalar LDS ----
#pragma unroll
        for (int k5 = 0; k5 < 5; k5++) {
            u32 a[4][4];
#pragma unroll
            for (int m = 0; m < 4; m++)
                ldmx4(a[m], As_b + (u32)(((m * 16 + lrow) * AST + k5 * 8 + lcol) << 2));
#pragma unroll
            for (int n = 0; n < 4; n++) {
                u32 b0 = Bu[off0[k5] + n * 8];
                u32 b1 = Bu[off1[k5] + n * 8];
#pragma unroll
                for (int m = 0; m < 4; m++)
                    mma_tf32(acc[m][n], a[m], b0, b1);
            }
        }
    }

    // ---- epilogue: bias + float2 stores (fragment-native layout, verified) ----
#pragma unroll
    for (int m = 0; m < 4; m++) {
        const int oc0 = m * 16 + r_;
        const int oc1 = oc0 + 8;
        const float bo0 = g_bias[oc0];
        const float bo1 = g_bias[oc1];
        float* p0 = out + (((size_t)(b * 64 + oc0)) << 16) + (y << 8) + w * 32 + cc_ * 2;
        float* p1 = out + (((size_t)(b * 64 + oc1)) << 16) + (y << 8) + w * 32 + cc_ * 2;
#pragma unroll
        for (int n = 0; n < 4; n++) {
            float2 s0 = make_float2(acc[m][n][0] + bo0, acc[m][n][1] + bo0);
            float2 s1 = make_float2(acc[m][n][2] + bo1, acc[m][n][3] + bo1);
            *(float2*)(p0 + n * 8) = s0;
            *(float2*)(p1 + n * 8) = s1;
        }
    }
}

}  // namespace

extern "C" void kernel_launch(void* const* d_in, const int* in_sizes, int n_in,
                              void* d_out, int out_size) {
    (void)in_sizes; (void)n_in; (void)out_size;
    const float* x    = (const float*)d_in[0];
    const float* lw   = (const float*)d_in[1];
    const float* lb   = (const float*)d_in[2];
    const float* w2aw = (const float*)d_in[3];
    const float* w2ab = (const float*)d_in[4];
    const float* w2bw = (const float*)d_in[5];
    const float* w2bb = (const float*)d_in[6];
    float* out = (float*)d_out;

    static int attr_set = 0;
    if (!attr_set) {
        cudaFuncSetAttribute(volterra_hmma,
                             cudaFuncAttributeMaxDynamicSharedMemorySize, SMEM_TOTAL);
        attr_set = 1;
    }
    precompute_kernel<<<64, 256>>>(lw, lb, w2aw, w2ab, w2bw, w2bb);
    volterra_hmma<<<2048, 256, SMEM_TOTAL>>>(x, out);
}

// round 9
// speedup vs baseline: 1.3832x; 1.3832x over previous
#include <cuda_runtime.h>
#include <cstdint>

namespace {

typedef unsigned int u32;

constexpr int AST = 44;                    // A smem row stride (words)
constexpr int BST = 44;                    // B smem row stride (words)
constexpr int A_WORDS = 64 * AST;          // 2816 per buffer
constexpr int B_WORDS = 256 * BST;         // 11264 per buffer
constexpr int SMEM_TOTAL = (2 * A_WORDS + 2 * B_WORDS) * 4;  // 112640 B

// Packed weights: tf32 (rna) bits, row oc (64), col k = i*10 + t (640).
// taps 0..8 = conv3x3 (ky*3+kx), tap 9 = collapsed quadratic matrix M[o][i].
__device__ u32 g_A[64 * 640];
__device__ float g_bias[64];

__device__ __forceinline__ u32 to_tf32(float f) {
    u32 r;
    asm("cvt.rna.tf32.f32 %0, %1;" : "=r"(r) : "f"(f));
    return r;
}

__device__ __forceinline__ void mma_tf32(float* d, const u32* a, u32 b0, u32 b1) {
    asm volatile(
        "mma.sync.aligned.m16n8k8.row.col.f32.tf32.tf32.f32 "
        "{%0,%1,%2,%3}, {%4,%5,%6,%7}, {%8,%9}, {%0,%1,%2,%3};"
        : "+f"(d[0]), "+f"(d[1]), "+f"(d[2]), "+f"(d[3])
        : "r"(a[0]), "r"(a[1]), "r"(a[2]), "r"(a[3]), "r"(b0), "r"(b1));
}

__device__ __forceinline__ void ldmx4(u32* r, u32 addr) {
    asm volatile("ldmatrix.sync.aligned.m8n8.x4.shared.b16 {%0,%1,%2,%3}, [%4];"
                 : "=r"(r[0]), "=r"(r[1]), "=r"(r[2]), "=r"(r[3]) : "r"(addr));
}

__device__ __forceinline__ u32 smem_u32(const void* p) {
    u32 a;
    asm("{ .reg .u64 t; cvta.to.shared.u64 t, %1; cvt.u32.u64 %0, t; }" : "=r"(a) : "l"(p));
    return a;
}

__device__ __forceinline__ void cp_async16(u32 dst, const void* src) {
    asm volatile("cp.async.cg.shared.global [%0], [%1], 16;"
                 :: "r"(dst), "l"(src) : "memory");
}

// grid 64 (channel i) x 256 threads (64 oc x 4 q-slices)
__global__ void precompute_kernel(const float* __restrict__ lw,
                                  const float* __restrict__ lb,
                                  const float* __restrict__ w2aw,
                                  const float* __restrict__ w2ab,
                                  const float* __restrict__ w2bw,
                                  const float* __restrict__ w2bb) {
    const int i = blockIdx.x;
    const int o = (int)threadIdx.x & 63;
    const int qq = (int)threadIdx.x >> 6;
    __shared__ float red[4][64];

    {
        const float* wb = w2bw + qq * 4096 + o * 64;
        const float* wa = w2aw + qq * 4096 + i;
        float m = 0.f;
#pragma unroll 8
        for (int mm = 0; mm < 64; mm++) m = fmaf(wb[mm], wa[mm * 64], m);
        red[qq][o] = m;
    }
    __syncthreads();

    if (qq == 0) {
        float w[10];
#pragma unroll
        for (int t = 0; t < 9; t++) w[t] = lw[(o * 64 + i) * 9 + t];
        w[9] = ((red[0][o] + red[1][o]) + (red[2][o] + red[3][o]));  // Sn tap
#pragma unroll
        for (int t = 0; t < 10; t++)
            g_A[o * 640 + i * 10 + t] = to_tf32(w[t]);

        if (i == 0) {
            float c = 0.f;
            for (int q = 0; q < 4; q++) {
                const float* wb = w2bw + q * 4096 + o * 64;
                const float* ab = w2ab + q * 64;
                float hh = 0.f;
#pragma unroll 8
                for (int mm = 0; mm < 64; mm++) hh = fmaf(wb[mm], ab[mm], hh);
                c += hh + w2bb[q * 64 + o];
            }
            g_bias[o] = lb[o] + c;
        }
    }
}

// Build features for 4 channels starting at xc4, pixel cx, into Bs[cx][0..39].
// Raw f32 bits (HW tf32-truncates the B operand). Identical math to R7.
__device__ __forceinline__ void build_B(u32* Bs, const float* xc4, int cx, int y,
                                        int oA, int oB, int oC, int xm1, int xp1) {
#pragma unroll
    for (int cp = 0; cp < 2; cp++) {
        u32 fv[20];
#pragma unroll
        for (int c2 = 0; c2 < 2; c2++) {
            const float* xc = xc4 + ((size_t)(cp * 2 + c2) << 16);
            float v[9];
            v[0] = __ldg(xc + oA + xm1); v[1] = __ldg(xc + oA + cx); v[2] = __ldg(xc + oA + xp1);
            v[3] = __ldg(xc + oB + xm1); v[4] = __ldg(xc + oB + cx); v[5] = __ldg(xc + oB + xp1);
            v[6] = __ldg(xc + oC + xm1); v[7] = __ldg(xc + oC + cx); v[8] = __ldg(xc + oC + xp1);

            float s = ((v[0] + v[1]) + (v[2] + v[3])) +
                      ((v[4] + v[5]) + (v[6] + v[7])) + v[8];
            float s2 = v[0] * v[0];
#pragma unroll
            for (int t = 1; t < 9; t++) s2 = fmaf(v[t], v[t], s2);
            const float Sn = fmaf(s, s, s2) * (1.0f / 90.0f);

            float f[10];
#pragma unroll
            for (int t = 0; t < 9; t++) f[t] = v[t];
            // zero-pad masks (conv taps only; Sn stays circular)
            if (y == 0)    { f[0] = 0.f; f[1] = 0.f; f[2] = 0.f; }
            if (y == 255)  { f[6] = 0.f; f[7] = 0.f; f[8] = 0.f; }
            if (cx == 0)   { f[0] = 0.f; f[3] = 0.f; f[6] = 0.f; }
            if (cx == 255) { f[2] = 0.f; f[5] = 0.f; f[8] = 0.f; }
            f[9] = Sn;
#pragma unroll
            for (int t = 0; t < 10; t++) fv[c2 * 10 + t] = __float_as_uint(f[t]);
        }
        u32* bp = Bs + cx * BST + cp * 20;
#pragma unroll
        for (int j = 0; j < 5; j++)
            *(uint4*)(bp + j * 4) =
                make_uint4(fv[4 * j], fv[4 * j + 1], fv[4 * j + 2], fv[4 * j + 3]);
    }
}

// 2048 CTAs (blockIdx.x = b*256 + y), 256 threads (8 warps), 2 CTAs/SM.
// Warp w owns output tile oc[0..63] x px[w*32..w*32+31].
// Double-buffered: Abuf[2] [64][44], Bbuf[2] [256][44] (pixel-major).
// Pipeline: build(0); { wait A(i); sync; issue A(i+1); MMA(i); build(i+1); }
__global__ __launch_bounds__(256, 2)
void volterra_hmma(const float* __restrict__ x, float* __restrict__ out) {
    extern __shared__ u32 smem[];
    const u32 As_b = smem_u32(smem);                 // + buf*A_WORDS*4
    u32* Bs0 = smem + 2 * A_WORDS;                   // + buf*B_WORDS
    const u32 Bs_b = As_b + 2 * A_WORDS * 4;

    const int tid = (int)threadIdx.x;
    const int w = tid >> 5;
    const int lane = tid & 31;
    const int b = (int)blockIdx.x >> 8;
    const int y = (int)blockIdx.x & 255;
    const int cx = tid;  // this thread's pixel column

    const int ym1 = (y - 1) & 255, yp1 = (y + 1) & 255;
    const int xm1 = (cx - 1) & 255, xp1 = (cx + 1) & 255;
    const int oA = (ym1 << 8), oB = (y << 8), oC = (yp1 << 8);
    const float* xb = x + ((size_t)b << 22);

    // ldmatrix lane-role
    const int lrow = lane & 15;
    const int lcol = (lane >> 4) * 4;

    float acc[4][4][4];
#pragma unroll
    for (int m = 0; m < 4; m++)
#pragma unroll
        for (int n = 0; n < 4; n++)
#pragma unroll
            for (int r = 0; r < 4; r++) acc[m][n][r] = 0.f;

    // A-stage roles: 640 quads over 256 threads, 3 passes
    int aq_off[3], aq_src[3];
#pragma unroll
    for (int p = 0; p < 3; p++) {
        int idx = tid + p * 256;
        int oc = idx / 10, j = idx - oc * 10;
        aq_off[p] = (oc * AST + j * 4) << 2;
        aq_src[p] = oc * 640 + j * 4;
    }

    // prologue: stage A(0), build B(0)
#pragma unroll
    for (int p = 0; p < 3; p++) {
        if (tid + p * 256 < 640)
            cp_async16(As_b + (u32)aq_off[p], g_A + aq_src[p]);
    }
    asm volatile("cp.async.commit_group;" ::: "memory");
    build_B(Bs0, xb, cx, y, oA, oB, oC, xm1, xp1);

#pragma unroll 1
    for (int iter = 0; iter < 16; iter++) {
        const int buf = iter & 1;
        const int nbuf = buf ^ 1;

        asm volatile("cp.async.wait_group 0;" ::: "memory");
        __syncthreads();  // A(iter) landed; B(iter) built; MMA(iter-1) reads done

        // issue A(iter+1) into the other buffer (overlaps MMA + build below)
        if (iter < 15) {
            const u32* gAn = g_A + (iter + 1) * 40;
            const u32 abase = As_b + (u32)(nbuf * A_WORDS * 4);
#pragma unroll
            for (int p = 0; p < 3; p++) {
                if (tid + p * 256 < 640)
                    cp_async16(abase + (u32)aq_off[p], gAn + aq_src[p]);
            }
        }
        asm volatile("cp.async.commit_group;" ::: "memory");

        // ---- MMA(iter): 5 k8-steps, fragments via ldmatrix.x4 ----
        const u32 Ab = As_b + (u32)(buf * A_WORDS * 4);
        const u32 Bb = Bs_b + (u32)(buf * B_WORDS * 4);
#pragma unroll
        for (int k5 = 0; k5 < 5; k5++) {
            u32 a[4][4];
#pragma unroll
            for (int m = 0; m < 4; m++)
                ldmx4(a[m], Ab + (u32)(((m * 16 + lrow) * AST + k5 * 8 + lcol) << 2));
#pragma unroll
            for (int np = 0; np < 2; np++) {
                u32 bb[4];
                ldmx4(bb, Bb + (u32)(((w * 32 + np * 16 + lrow) * BST + k5 * 8 + lcol) << 2));
#pragma unroll
                for (int m = 0; m < 4; m++) {
                    mma_tf32(acc[m][2 * np + 0], a[m], bb[0], bb[2]);
                    mma_tf32(acc[m][2 * np + 1], a[m], bb[1], bb[3]);
                }
            }
        }

        // ---- build B(iter+1) into the other buffer (LDGs hide under MMAs) ----
        if (iter < 15) {
            build_B(Bs0 + nbuf * B_WORDS, xb + ((size_t)((iter + 1) * 4) << 16),
                    cx, y, oA, oB, oC, xm1, xp1);
        }
    }

    // ---- epilogue: bias + float2 stores (fragment-native layout, verified) ----
    const int r_ = lane >> 2, cc_ = lane & 3;
#pragma unroll
    for (int m = 0; m < 4; m++) {
        const int oc0 = m * 16 + r_;
        const int oc1 = oc0 + 8;
        const float bo0 = g_bias[oc0];
        const float bo1 = g_bias[oc1];
        float* p0 = out + (((size_t)(b * 64 + oc0)) << 16) + (y << 8) + w * 32 + cc_ * 2;
        float* p1 = out + (((size_t)(b * 64 + oc1)) << 16) + (y << 8) + w * 32 + cc_ * 2;
#pragma unroll
        for (int n = 0; n < 4; n++) {
            float2 s0 = make_float2(acc[m][n][0] + bo0, acc[m][n][1] + bo0);
            float2 s1 = make_float2(acc[m][n][2] + bo1, acc[m][n][3] + bo1);
            *(float2*)(p0 + n * 8) = s0;
            *(float2*)(p1 + n * 8) = s1;
        }
    }
}

}  // namespace

extern "C" void kernel_launch(void* const* d_in, const int* in_sizes, int n_in,
                              void* d_out, int out_size) {
    (void)in_sizes; (void)n_in; (void)out_size;
    const float* x    = (const float*)d_in[0];
    const float* lw   = (const float*)d_in[1];
    const float* lb   = (const float*)d_in[2];
    const float* w2aw = (const float*)d_in[3];
    const float* w2ab = (const float*)d_in[4];
    const float* w2bw = (const float*)d_in[5];
    const float* w2bb = (const float*)d_in[6];
    float* out = (float*)d_out;

    static int attr_set = 0;
    if (!attr_set) {
        cudaFuncSetAttribute(volterra_hmma,
                             cudaFuncAttributeMaxDynamicSharedMemorySize, SMEM_TOTAL);
        attr_set = 1;
    }
    precompute_kernel<<<64, 256>>>(lw, lb, w2aw, w2ab, w2bw, w2bb);
    volterra_hmma<<<2048, 256, SMEM_TOTAL>>>(x, out);
}